// round 3
// baseline (speedup 1.0000x reference)
#include <cuda_runtime.h>
#include <math.h>

#define BBx 2
#define LLx 2048
#define HHx 8
#define PPx 64
#define DIx 512
#define NDx 16
#define QQx 300
#define QPx 320
#define LDZ 1040
#define NTOK 4096
#define NQx 600

__device__ __align__(16) float g_zx  [NTOK*LDZ];
__device__ __align__(16) float g_init[NQx*DIx];
__device__ __align__(16) float g_dA  [NTOK*HHx*QPx];
__device__ __align__(16) float g_dtB [NTOK*HHx*QPx];
__device__ __align__(16) float g_C   [NTOK*QPx];
__device__ __align__(16) float g_y   [NTOK*DIx];
__device__ __align__(16) float g_S   [NQx*DIx];
__device__ __align__(16) float g_kf  [NTOK*DIx];
__device__ __align__(16) float g_ln  [NQx*DIx];

__device__ __forceinline__ void ld4(const float* p, float* v) {
    float4 t = *(const float4*)p;
    v[0]=t.x; v[1]=t.y; v[2]=t.z; v[3]=t.w;
}

__global__ void zero_kernel() {
    int i = blockIdx.x*blockDim.x + threadIdx.x;
    const int NY = NTOK*DIx, NS = NQx*DIx;
    if (i < NY) g_y[i] = 0.f;
    int j = i - NY;
    if (j >= 0 && j < NS) g_S[j] = 0.f;
}

// C[M,N] = A[M,K] @ B[N,K]^T ; K % 16 == 0
__global__ __launch_bounds__(256) void sgemm_nt(
    int M, int N, int K,
    const float* __restrict__ A, const float* __restrict__ B,
    float* __restrict__ C, int ldc)
{
    __shared__ float As[16][132];
    __shared__ float Bs[16][68];
    const int tid = threadIdx.x;
    const int tx = tid & 15, ty = tid >> 4;
    const int m0 = blockIdx.y*128, n0 = blockIdx.x*64;
    float acc[8][4];
#pragma unroll
    for (int i=0;i<8;i++)
#pragma unroll
        for (int j=0;j<4;j++) acc[i][j]=0.f;

    for (int k0=0;k0<K;k0+=16) {
#pragma unroll
        for (int i=0;i<2;i++) {
            int idx = tid + i*256;
            int ar = idx >> 2, ac = (idx & 3) << 2;
            int gm = m0 + ar;
            float4 v = make_float4(0.f,0.f,0.f,0.f);
            if (gm < M) v = *(const float4*)(A + (size_t)gm*K + k0 + ac);
            As[ac+0][ar]=v.x; As[ac+1][ar]=v.y; As[ac+2][ar]=v.z; As[ac+3][ar]=v.w;
        }
        {
            int br = tid >> 2, bc = (tid & 3) << 2;
            int gn = n0 + br;
            float4 v = make_float4(0.f,0.f,0.f,0.f);
            if (gn < N) v = *(const float4*)(B + (size_t)gn*K + k0 + bc);
            Bs[bc+0][br]=v.x; Bs[bc+1][br]=v.y; Bs[bc+2][br]=v.z; Bs[bc+3][br]=v.w;
        }
        __syncthreads();
#pragma unroll
        for (int kk=0;kk<16;kk++) {
            float a[8], bb[4];
#pragma unroll
            for (int i=0;i<8;i++) a[i] = As[kk][ty*8+i];
            float4 bv = *(const float4*)&Bs[kk][tx*4];
            bb[0]=bv.x; bb[1]=bv.y; bb[2]=bv.z; bb[3]=bv.w;
#pragma unroll
            for (int i=0;i<8;i++)
#pragma unroll
                for (int j=0;j<4;j++) acc[i][j] = fmaf(a[i], bb[j], acc[i][j]);
        }
        __syncthreads();
    }
#pragma unroll
    for (int i=0;i<8;i++) {
        int gm = m0 + ty*8 + i;
        if (gm < M)
#pragma unroll
            for (int j=0;j<4;j++) {
                int gn = n0 + tx*4 + j;
                if (gn < N) C[(size_t)gm*ldc + gn] = acc[i][j];
            }
    }
}

// per-token: B,C,dt -> g_dA=exp(dt*A), g_dtB=dt*B, g_C
__global__ __launch_bounds__(QPx) void precompute_kernel(
    const float* __restrict__ dist, const float* __restrict__ W_bc,
    const float* __restrict__ W_dt, const float* __restrict__ dt_bias,
    const float* __restrict__ A_log)
{
    const int bt = blockIdx.x;
    const int n  = threadIdx.x;
    __shared__ float swbc[32], swdt[128], sdtb[8], sA[8], stok[10];
    if (n < 32) swbc[n] = W_bc[n];
    if (n >= 32 && n < 160) swdt[n-32] = W_dt[n-32];
    if (n >= 160 && n < 168) {
        sdtb[n-160] = dt_bias[n-160];
        sA[n-160]   = -expf(A_log[n-160]);
    }
    if (n >= 168 && n < 178) stok[n-168] = g_zx[(size_t)bt*LDZ + 1024 + (n-168)];
    __syncthreads();

    const bool valid = (n < QQx);
    float d[16];
    if (valid) {
        const float* dp = dist + ((size_t)bt*QQx + n)*NDx;
        ld4(dp,d); ld4(dp+4,d+4); ld4(dp+8,d+8); ld4(dp+12,d+12);
    } else {
#pragma unroll
        for (int i=0;i<16;i++) d[i]=0.f;
    }
    float bc0=0.f, bc1=0.f;
#pragma unroll
    for (int i=0;i<16;i++) {
        bc0 = fmaf(d[i], swbc[i],    bc0);
        bc1 = fmaf(d[i], swbc[16+i], bc1);
    }
    float Bv = bc0 + stok[0];
    float Cv = bc1 + stok[1];
    g_C[(size_t)bt*QPx + n] = valid ? Cv : 0.f;
#pragma unroll
    for (int h=0;h<8;h++) {
        float db = 0.f;
#pragma unroll
        for (int i=0;i<16;i++) db = fmaf(d[i], swdt[h*16+i], db);
        float v  = db + stok[2+h] + sdtb[h];
        float dt = (v > 20.f) ? v : log1pf(expf(v));
        size_t o = ((size_t)bt*HHx + h)*QPx + n;
        g_dA[o]  = valid ? expf(dt*sA[h]) : 0.f;
        g_dtB[o] = valid ? dt*Bv : 0.f;
    }
}

// bidirectional scan: 128 blocks = (pg4, h8, b2, dir2); 320 thr; 4p x 4n per thread
__global__ __launch_bounds__(320) void scan_kernel() {
    const int bx  = blockIdx.x;
    const int pg  = bx & 3;
    const int h   = (bx >> 2) & 7;
    const int b   = (bx >> 5) & 1;
    const int dir = (bx >> 6) & 1;

    const int tid = threadIdx.x, w = tid >> 5, lane = tid & 31;
    const int p_grp = lane >> 3, n_sub = lane & 7;
    const int n0 = w*32 + n_sub*4;
    const int p0 = pg*16 + p_grp*4;

    float S[4][4];
#pragma unroll
    for (int pi=0;pi<4;pi++)
#pragma unroll
        for (int j=0;j<4;j++) {
            int n = n0 + j;
            S[pi][j] = (n < QQx) ? g_init[((size_t)(b*QQx+n))*DIx + h*PPx + p0 + pi] : 0.f;
        }

    const int bL = b*LLx;
    const int t0 = dir ? (LLx-1) : 0;
    const int stp = dir ? -1 : 1;
    const long dA_s = (long)stp*(HHx*QPx);
    const long dC_s = (long)stp*QPx;
    const long dX_s = (long)stp*LDZ;
    const long dY_s = (long)stp*DIx;

    const float* pA = g_dA  + ((size_t)(bL+t0)*HHx + h)*QPx + n0;
    const float* pU = g_dtB + ((size_t)(bL+t0)*HHx + h)*QPx + n0;
    const float* pC = g_C   + (size_t)(bL+t0)*QPx + n0;
    const float* pX = g_zx  + (size_t)(bL+t0)*LDZ + DIx + h*PPx + p0;
    float*       pY = g_y   + (size_t)(bL+t0)*DIx + h*PPx + p0;

    float av[4], uv[4], cv[4], xv[4];
    ld4(pA,av); ld4(pU,uv); ld4(pC,cv); ld4(pX,xv);

    for (int s=0;s<LLx;s++) {
        float nav[4], nuv[4], ncv[4], nxv[4];
        const bool more = (s < LLx-1);
        if (more) { ld4(pA+dA_s,nav); ld4(pU+dA_s,nuv); ld4(pC+dC_s,ncv); ld4(pX+dX_s,nxv); }

        float yp[4];
#pragma unroll
        for (int pi=0;pi<4;pi++) {
            float xx = xv[pi];
            float acc = 0.f;
#pragma unroll
            for (int j=0;j<4;j++) {
                float sv = fmaf(S[pi][j], av[j], uv[j]*xx);
                S[pi][j] = sv;
                acc = fmaf(sv, cv[j], acc);
            }
            yp[pi] = acc;
        }
#pragma unroll
        for (int pi=0;pi<4;pi++) {
            yp[pi] += __shfl_xor_sync(0xffffffffu, yp[pi], 4);
            yp[pi] += __shfl_xor_sync(0xffffffffu, yp[pi], 2);
            yp[pi] += __shfl_xor_sync(0xffffffffu, yp[pi], 1);
        }
        if (n_sub == 0) {
            atomicAdd(pY+0, 0.5f*yp[0]);
            atomicAdd(pY+1, 0.5f*yp[1]);
            atomicAdd(pY+2, 0.5f*yp[2]);
            atomicAdd(pY+3, 0.5f*yp[3]);
        }
        if (more) {
            pA += dA_s; pU += dA_s; pC += dC_s; pX += dX_s; pY += dY_s;
#pragma unroll
            for (int j=0;j<4;j++) { av[j]=nav[j]; uv[j]=nuv[j]; cv[j]=ncv[j]; xv[j]=nxv[j]; }
        }
    }
#pragma unroll
    for (int pi=0;pi<4;pi++)
#pragma unroll
        for (int j=0;j<4;j++) {
            int n = n0 + j;
            if (n < QQx)
                atomicAdd(&g_S[((size_t)(b*QQx+n))*DIx + h*PPx + p0 + pi], 0.5f*S[pi][j]);
        }
}

__global__ __launch_bounds__(256) void gate_rms_kernel(
    const float* __restrict__ Dv, const float* __restrict__ knw)
{
    const int row = blockIdx.x, tid = threadIdx.x;
    float g[2]; float ss = 0.f;
#pragma unroll
    for (int e2=0;e2<2;e2++) {
        int e = tid + e2*256;
        float y = g_y [(size_t)row*DIx + e];
        float x = g_zx[(size_t)row*LDZ + DIx + e];
        float z = g_zx[(size_t)row*LDZ + e];
        float gg = (y + x*Dv[e>>6]) * (z / (1.f + expf(-z)));
        g[e2] = gg;
        ss += gg*gg;
    }
#pragma unroll
    for (int o=16;o;o>>=1) ss += __shfl_xor_sync(0xffffffffu, ss, o);
    __shared__ float red[8];
    if ((tid & 31) == 0) red[tid>>5] = ss;
    __syncthreads();
    if (tid == 0) {
        float tot = 0.f;
#pragma unroll
        for (int i=0;i<8;i++) tot += red[i];
        red[0] = rsqrtf(tot/512.f + 1e-5f);
    }
    __syncthreads();
    float sc = red[0];
#pragma unroll
    for (int e2=0;e2<2;e2++) {
        int e = tid + e2*256;
        g_kf[(size_t)row*DIx + e] = g[e2]*sc*knw[e];
    }
}

__global__ __launch_bounds__(256) void lnorm_kernel(
    const float* __restrict__ wn, const float* __restrict__ bn)
{
    const int row = blockIdx.x, tid = threadIdx.x;
    float v[2]; float s1 = 0.f, s2 = 0.f;
#pragma unroll
    for (int e2=0;e2<2;e2++) {
        int e = tid + e2*256;
        float x = g_S[(size_t)row*DIx + e];
        v[e2] = x; s1 += x; s2 += x*x;
    }
#pragma unroll
    for (int o=16;o;o>>=1) {
        s1 += __shfl_xor_sync(0xffffffffu, s1, o);
        s2 += __shfl_xor_sync(0xffffffffu, s2, o);
    }
    __shared__ float r1[8], r2[8];
    if ((tid & 31) == 0) { r1[tid>>5] = s1; r2[tid>>5] = s2; }
    __syncthreads();
    __shared__ float smu, sisd;
    if (tid == 0) {
        float a=0.f, b=0.f;
#pragma unroll
        for (int i=0;i<8;i++) { a += r1[i]; b += r2[i]; }
        float mu = a/512.f;
        smu = mu;
        sisd = rsqrtf(b/512.f - mu*mu + 1e-5f);
    }
    __syncthreads();
    float mu = smu, isd = sisd;
#pragma unroll
    for (int e2=0;e2<2;e2++) {
        int e = tid + e2*256;
        g_ln[(size_t)row*DIx + e] = (v[e2]-mu)*isd*wn[e] + bn[e];
    }
}

extern "C" void kernel_launch(void* const* d_in, const int* in_sizes, int n_in,
                              void* d_out, int out_size) {
    const float* in_key    = (const float*)d_in[0];
    const float* in_query  = (const float*)d_in[1];
    const float* dist      = (const float*)d_in[2];
    const float* W_key     = (const float*)d_in[3];
    const float* W_query   = (const float*)d_in[4];
    const float* W_bc      = (const float*)d_in[5];
    const float* W_dt      = (const float*)d_in[6];
    const float* dt_bias   = (const float*)d_in[7];
    const float* A_log     = (const float*)d_in[8];
    const float* Dv        = (const float*)d_in[9];
    const float* W_out_key = (const float*)d_in[10];
    const float* W_out_qry = (const float*)d_in[11];
    const float* key_nw    = (const float*)d_in[12];
    const float* q_nw      = (const float*)d_in[13];
    const float* q_nb      = (const float*)d_in[14];
    float* out = (float*)d_out;

    float *p_zx, *p_init, *p_kf, *p_ln;
    cudaGetSymbolAddress((void**)&p_zx,   g_zx);
    cudaGetSymbolAddress((void**)&p_init, g_init);
    cudaGetSymbolAddress((void**)&p_kf,   g_kf);
    cudaGetSymbolAddress((void**)&p_ln,   g_ln);

    zero_kernel<<<(NTOK*DIx + NQx*DIx + 255)/256, 256>>>();
    sgemm_nt<<<dim3(17,32), 256>>>(NTOK, 1034, 256, in_key,   W_key,   p_zx,   LDZ);
    sgemm_nt<<<dim3(8,5),   256>>>(NQx,  512,  256, in_query, W_query, p_init, DIx);
    precompute_kernel<<<NTOK, QPx>>>(dist, W_bc, W_dt, dt_bias, A_log);
    scan_kernel<<<128, 320>>>();
    gate_rms_kernel<<<NTOK, 256>>>(Dv, key_nw);
    lnorm_kernel<<<NQx, 256>>>(q_nw, q_nb);
    sgemm_nt<<<dim3(4,32), 256>>>(NTOK, 256, 512, p_kf, W_out_key, out, 256);
    sgemm_nt<<<dim3(4,5),  256>>>(NQx,  256, 512, p_ln, W_out_qry, out + (size_t)NTOK*256, 256);
}

// round 4
// speedup vs baseline: 1.3794x; 1.3794x over previous
#include <cuda_runtime.h>
#include <math.h>

#define BBx 2
#define LLx 2048
#define HHx 8
#define PPx 64
#define DIx 512
#define NDx 16
#define QQx 300
#define QPx 320
#define LDZ 1040
#define NTOK 4096
#define NQx 600

__device__ __align__(16) float g_zx  [NTOK*LDZ];
__device__ __align__(16) float g_init[NQx*DIx];
__device__ __align__(16) float g_dA  [NTOK*HHx*QPx];
__device__ __align__(16) float g_dtB [NTOK*HHx*QPx];
__device__ __align__(16) float g_C   [NTOK*QPx];
__device__ __align__(16) float g_y   [NTOK*DIx];
__device__ __align__(16) float g_S   [NQx*DIx];
__device__ __align__(16) float g_kf  [NTOK*DIx];
__device__ __align__(16) float g_ln  [NQx*DIx];

__device__ __forceinline__ void ld4(const float* p, float* v) {
    float4 t = *(const float4*)p;
    v[0]=t.x; v[1]=t.y; v[2]=t.z; v[3]=t.w;
}

__global__ void zero_kernel() {
    int i = blockIdx.x*blockDim.x + threadIdx.x;
    const int NY = NTOK*DIx, NS = NQx*DIx;
    if (i < NY) g_y[i] = 0.f;
    int j = i - NY;
    if (j >= 0 && j < NS) g_S[j] = 0.f;
}

// C[M,N] = A[M,K] @ B[N,K]^T ; K % 16 == 0
__global__ __launch_bounds__(256) void sgemm_nt(
    int M, int N, int K,
    const float* __restrict__ A, const float* __restrict__ B,
    float* __restrict__ C, int ldc)
{
    __shared__ float As[16][132];
    __shared__ float Bs[16][68];
    const int tid = threadIdx.x;
    const int tx = tid & 15, ty = tid >> 4;
    const int m0 = blockIdx.y*128, n0 = blockIdx.x*64;
    float acc[8][4];
#pragma unroll
    for (int i=0;i<8;i++)
#pragma unroll
        for (int j=0;j<4;j++) acc[i][j]=0.f;

    for (int k0=0;k0<K;k0+=16) {
#pragma unroll
        for (int i=0;i<2;i++) {
            int idx = tid + i*256;
            int ar = idx >> 2, ac = (idx & 3) << 2;
            int gm = m0 + ar;
            float4 v = make_float4(0.f,0.f,0.f,0.f);
            if (gm < M) v = *(const float4*)(A + (size_t)gm*K + k0 + ac);
            As[ac+0][ar]=v.x; As[ac+1][ar]=v.y; As[ac+2][ar]=v.z; As[ac+3][ar]=v.w;
        }
        {
            int br = tid >> 2, bc = (tid & 3) << 2;
            int gn = n0 + br;
            float4 v = make_float4(0.f,0.f,0.f,0.f);
            if (gn < N) v = *(const float4*)(B + (size_t)gn*K + k0 + bc);
            Bs[bc+0][br]=v.x; Bs[bc+1][br]=v.y; Bs[bc+2][br]=v.z; Bs[bc+3][br]=v.w;
        }
        __syncthreads();
#pragma unroll
        for (int kk=0;kk<16;kk++) {
            float a[8], bb[4];
#pragma unroll
            for (int i=0;i<8;i++) a[i] = As[kk][ty*8+i];
            float4 bv = *(const float4*)&Bs[kk][tx*4];
            bb[0]=bv.x; bb[1]=bv.y; bb[2]=bv.z; bb[3]=bv.w;
#pragma unroll
            for (int i=0;i<8;i++)
#pragma unroll
                for (int j=0;j<4;j++) acc[i][j] = fmaf(a[i], bb[j], acc[i][j]);
        }
        __syncthreads();
    }
#pragma unroll
    for (int i=0;i<8;i++) {
        int gm = m0 + ty*8 + i;
        if (gm < M)
#pragma unroll
            for (int j=0;j<4;j++) {
                int gn = n0 + tx*4 + j;
                if (gn < N) C[(size_t)gm*ldc + gn] = acc[i][j];
            }
    }
}

// per-token: B,C,dt -> g_dA=exp(dt*A), g_dtB=dt*B, g_C
__global__ __launch_bounds__(QPx) void precompute_kernel(
    const float* __restrict__ dist, const float* __restrict__ W_bc,
    const float* __restrict__ W_dt, const float* __restrict__ dt_bias,
    const float* __restrict__ A_log)
{
    const int bt = blockIdx.x;
    const int n  = threadIdx.x;
    __shared__ float swbc[32], swdt[128], sdtb[8], sA[8], stok[10];
    if (n < 32) swbc[n] = W_bc[n];
    if (n >= 32 && n < 160) swdt[n-32] = W_dt[n-32];
    if (n >= 160 && n < 168) {
        sdtb[n-160] = dt_bias[n-160];
        sA[n-160]   = -expf(A_log[n-160]);
    }
    if (n >= 168 && n < 178) stok[n-168] = g_zx[(size_t)bt*LDZ + 1024 + (n-168)];
    __syncthreads();

    const bool valid = (n < QQx);
    float d[16];
    if (valid) {
        const float* dp = dist + ((size_t)bt*QQx + n)*NDx;
        ld4(dp,d); ld4(dp+4,d+4); ld4(dp+8,d+8); ld4(dp+12,d+12);
    } else {
#pragma unroll
        for (int i=0;i<16;i++) d[i]=0.f;
    }
    float bc0=0.f, bc1=0.f;
#pragma unroll
    for (int i=0;i<16;i++) {
        bc0 = fmaf(d[i], swbc[i],    bc0);
        bc1 = fmaf(d[i], swbc[16+i], bc1);
    }
    float Bv = bc0 + stok[0];
    float Cv = bc1 + stok[1];
    g_C[(size_t)bt*QPx + n] = valid ? Cv : 0.f;
#pragma unroll
    for (int h=0;h<8;h++) {
        float db = 0.f;
#pragma unroll
        for (int i=0;i<16;i++) db = fmaf(d[i], swdt[h*16+i], db);
        float v  = db + stok[2+h] + sdtb[h];
        float dt = (v > 20.f) ? v : log1pf(expf(v));
        size_t o = ((size_t)bt*HHx + h)*QPx + n;
        g_dA[o]  = valid ? expf(dt*sA[h]) : 0.f;
        g_dtB[o] = valid ? dt*Bv : 0.f;
    }
}

// bidirectional scan v2: 128 blocks = (pg4, h8, b2, dir2); 640 thr (20 warps);
// thread tile 2p x 4n; 2-deep software pipeline; warp-local n reduction.
__global__ __launch_bounds__(640) void scan_kernel() {
    const int bx  = blockIdx.x;
    const int pg  = bx & 3;
    const int h   = (bx >> 2) & 7;
    const int b   = (bx >> 5) & 1;
    const int dir = (bx >> 6) & 1;

    const int tid = threadIdx.x, w = tid >> 5, lane = tid & 31;
    const int wn = w >> 1, wp = w & 1;          // wn: n-range 0..9, wp: p-octet 0..1
    const int p_pair = lane >> 3, n_sub = lane & 7;
    const int n0 = wn*32 + n_sub*4;
    const int p0 = pg*16 + wp*8 + p_pair*2;

    float S0[4], S1[4];
#pragma unroll
    for (int j=0;j<4;j++) {
        int n = n0 + j;
        if (n < QQx) {
            const float* ip = &g_init[((size_t)(b*QQx+n))*DIx + h*PPx + p0];
            S0[j] = ip[0]; S1[j] = ip[1];
        } else { S0[j] = 0.f; S1[j] = 0.f; }
    }

    const int bL = b*LLx;
    const int t0 = dir ? (LLx-1) : 0;
    const int stp = dir ? -1 : 1;
    const long dA_s = (long)stp*(HHx*QPx);
    const long dC_s = (long)stp*QPx;
    const long dX_s = (long)stp*LDZ;
    const long dY_s = (long)stp*DIx;

    const float* bA = g_dA  + ((size_t)(bL+t0)*HHx + h)*QPx + n0;
    const float* bU = g_dtB + ((size_t)(bL+t0)*HHx + h)*QPx + n0;
    const float* bC = g_C   + (size_t)(bL+t0)*QPx + n0;
    const float* bX = g_zx  + (size_t)(bL+t0)*LDZ + DIx + h*PPx + p0;
    float*       pY = g_y   + (size_t)(bL+t0)*DIx + h*PPx + p0;

    // prologue: load steps 0 and 1
    float avA[4], uvA[4], cvA[4], xvA[2];
    float avB[4], uvB[4], cvB[4], xvB[2];
    ld4(bA, avA); ld4(bU, uvA); ld4(bC, cvA);
    { float2 t = *(const float2*)bX; xvA[0]=t.x; xvA[1]=t.y; }
    ld4(bA+dA_s, avB); ld4(bU+dA_s, uvB); ld4(bC+dC_s, cvB);
    { float2 t = *(const float2*)(bX+dX_s); xvB[0]=t.x; xvB[1]=t.y; }

    // prefetch pointers -> step 2
    const float* pA = bA + 2*dA_s;
    const float* pU = bU + 2*dA_s;
    const float* pC = bC + 2*dC_s;
    const float* pX = bX + 2*dX_s;

#define SCAN_STEP(AV,UV,CV,XV)                                        \
    {                                                                 \
        float yp0 = 0.f, yp1 = 0.f;                                   \
        _Pragma("unroll")                                             \
        for (int j=0;j<4;j++) {                                       \
            float s0 = fmaf(S0[j], AV[j], UV[j]*XV[0]);               \
            float s1 = fmaf(S1[j], AV[j], UV[j]*XV[1]);               \
            S0[j]=s0; S1[j]=s1;                                       \
            yp0 = fmaf(s0, CV[j], yp0);                               \
            yp1 = fmaf(s1, CV[j], yp1);                               \
        }                                                             \
        yp0 += __shfl_xor_sync(0xffffffffu, yp0, 4);                  \
        yp1 += __shfl_xor_sync(0xffffffffu, yp1, 4);                  \
        yp0 += __shfl_xor_sync(0xffffffffu, yp0, 2);                  \
        yp1 += __shfl_xor_sync(0xffffffffu, yp1, 2);                  \
        yp0 += __shfl_xor_sync(0xffffffffu, yp0, 1);                  \
        yp1 += __shfl_xor_sync(0xffffffffu, yp1, 1);                  \
        if (n_sub == 0) {                                             \
            atomicAdd(pY,   0.5f*yp0);                                \
            atomicAdd(pY+1, 0.5f*yp1);                                \
        }                                                             \
        pY += dY_s;                                                   \
    }

#define SCAN_PREFETCH(AV,UV,CV,XV)                                    \
    {                                                                 \
        ld4(pA, AV); ld4(pU, UV); ld4(pC, CV);                        \
        float2 t = *(const float2*)pX; XV[0]=t.x; XV[1]=t.y;          \
        pA += dA_s; pU += dA_s; pC += dC_s; pX += dX_s;               \
    }

    for (int s = 0; s < LLx; s += 2) {
        SCAN_STEP(avA, uvA, cvA, xvA);
        if (s < LLx-2) SCAN_PREFETCH(avA, uvA, cvA, xvA);
        SCAN_STEP(avB, uvB, cvB, xvB);
        if (s < LLx-3) SCAN_PREFETCH(avB, uvB, cvB, xvB);
    }
#undef SCAN_STEP
#undef SCAN_PREFETCH

#pragma unroll
    for (int j=0;j<4;j++) {
        int n = n0 + j;
        if (n < QQx) {
            float* sp = &g_S[((size_t)(b*QQx+n))*DIx + h*PPx + p0];
            atomicAdd(sp,   0.5f*S0[j]);
            atomicAdd(sp+1, 0.5f*S1[j]);
        }
    }
}

__global__ __launch_bounds__(256) void gate_rms_kernel(
    const float* __restrict__ Dv, const float* __restrict__ knw)
{
    const int row = blockIdx.x, tid = threadIdx.x;
    float g[2]; float ss = 0.f;
#pragma unroll
    for (int e2=0;e2<2;e2++) {
        int e = tid + e2*256;
        float y = g_y [(size_t)row*DIx + e];
        float x = g_zx[(size_t)row*LDZ + DIx + e];
        float z = g_zx[(size_t)row*LDZ + e];
        float gg = (y + x*Dv[e>>6]) * (z / (1.f + expf(-z)));
        g[e2] = gg;
        ss += gg*gg;
    }
#pragma unroll
    for (int o=16;o;o>>=1) ss += __shfl_xor_sync(0xffffffffu, ss, o);
    __shared__ float red[8];
    if ((tid & 31) == 0) red[tid>>5] = ss;
    __syncthreads();
    if (tid == 0) {
        float tot = 0.f;
#pragma unroll
        for (int i=0;i<8;i++) tot += red[i];
        red[0] = rsqrtf(tot/512.f + 1e-5f);
    }
    __syncthreads();
    float sc = red[0];
#pragma unroll
    for (int e2=0;e2<2;e2++) {
        int e = tid + e2*256;
        g_kf[(size_t)row*DIx + e] = g[e2]*sc*knw[e];
    }
}

__global__ __launch_bounds__(256) void lnorm_kernel(
    const float* __restrict__ wn, const float* __restrict__ bn)
{
    const int row = blockIdx.x, tid = threadIdx.x;
    float v[2]; float s1 = 0.f, s2 = 0.f;
#pragma unroll
    for (int e2=0;e2<2;e2++) {
        int e = tid + e2*256;
        float x = g_S[(size_t)row*DIx + e];
        v[e2] = x; s1 += x; s2 += x*x;
    }
#pragma unroll
    for (int o=16;o;o>>=1) {
        s1 += __shfl_xor_sync(0xffffffffu, s1, o);
        s2 += __shfl_xor_sync(0xffffffffu, s2, o);
    }
    __shared__ float r1[8], r2[8];
    if ((tid & 31) == 0) { r1[tid>>5] = s1; r2[tid>>5] = s2; }
    __syncthreads();
    __shared__ float smu, sisd;
    if (tid == 0) {
        float a=0.f, bq=0.f;
#pragma unroll
        for (int i=0;i<8;i++) { a += r1[i]; bq += r2[i]; }
        float mu = a/512.f;
        smu = mu;
        sisd = rsqrtf(bq/512.f - mu*mu + 1e-5f);
    }
    __syncthreads();
    float mu = smu, isd = sisd;
#pragma unroll
    for (int e2=0;e2<2;e2++) {
        int e = tid + e2*256;
        g_ln[(size_t)row*DIx + e] = (v[e2]-mu)*isd*wn[e] + bn[e];
    }
}

extern "C" void kernel_launch(void* const* d_in, const int* in_sizes, int n_in,
                              void* d_out, int out_size) {
    const float* in_key    = (const float*)d_in[0];
    const float* in_query  = (const float*)d_in[1];
    const float* dist      = (const float*)d_in[2];
    const float* W_key     = (const float*)d_in[3];
    const float* W_query   = (const float*)d_in[4];
    const float* W_bc      = (const float*)d_in[5];
    const float* W_dt      = (const float*)d_in[6];
    const float* dt_bias   = (const float*)d_in[7];
    const float* A_log     = (const float*)d_in[8];
    const float* Dv        = (const float*)d_in[9];
    const float* W_out_key = (const float*)d_in[10];
    const float* W_out_qry = (const float*)d_in[11];
    const float* key_nw    = (const float*)d_in[12];
    const float* q_nw      = (const float*)d_in[13];
    const float* q_nb      = (const float*)d_in[14];
    float* out = (float*)d_out;

    float *p_zx, *p_init, *p_kf, *p_ln;
    cudaGetSymbolAddress((void**)&p_zx,   g_zx);
    cudaGetSymbolAddress((void**)&p_init, g_init);
    cudaGetSymbolAddress((void**)&p_kf,   g_kf);
    cudaGetSymbolAddress((void**)&p_ln,   g_ln);

    zero_kernel<<<(NTOK*DIx + NQx*DIx + 255)/256, 256>>>();
    sgemm_nt<<<dim3(17,32), 256>>>(NTOK, 1034, 256, in_key,   W_key,   p_zx,   LDZ);
    sgemm_nt<<<dim3(8,5),   256>>>(NQx,  512,  256, in_query, W_query, p_init, DIx);
    precompute_kernel<<<NTOK, QPx>>>(dist, W_bc, W_dt, dt_bias, A_log);
    scan_kernel<<<128, 640>>>();
    gate_rms_kernel<<<NTOK, 256>>>(Dv, key_nw);
    lnorm_kernel<<<NQx, 256>>>(q_nw, q_nb);
    sgemm_nt<<<dim3(4,32), 256>>>(NTOK, 256, 512, p_kf, W_out_key, out, 256);
    sgemm_nt<<<dim3(4,5),  256>>>(NQx,  256, 512, p_ln, W_out_qry, out + (size_t)NTOK*256, 256);
}

// round 5
// speedup vs baseline: 1.9409x; 1.4071x over previous
#include <cuda_runtime.h>
#include <math.h>

#define BBx 2
#define LLx 2048
#define HHx 8
#define PPx 64
#define DIx 512
#define NDx 16
#define QQx 300
#define QPx 320
#define LDZ 1040
#define NTOK 4096
#define NQx 600

__device__ __align__(16) float g_zx  [NTOK*LDZ];
__device__ __align__(16) float g_init[NQx*DIx];
__device__ __align__(16) float g_dA  [NTOK*HHx*QPx];
__device__ __align__(16) float g_dtB [NTOK*HHx*QPx];
__device__ __align__(16) float g_C   [NTOK*QPx];
__device__ __align__(16) float g_y   [NTOK*DIx];
__device__ __align__(16) float g_S   [NQx*DIx];
__device__ __align__(16) float g_kf  [NTOK*DIx];
__device__ __align__(16) float g_ln  [NQx*DIx];

__device__ __forceinline__ void ld4(const float* p, float* v) {
    float4 t = *(const float4*)p;
    v[0]=t.x; v[1]=t.y; v[2]=t.z; v[3]=t.w;
}

__global__ void zero_kernel() {
    int i = blockIdx.x*blockDim.x + threadIdx.x;
    const int NY = NTOK*DIx, NS = NQx*DIx;
    if (i < NY) g_y[i] = 0.f;
    int j = i - NY;
    if (j >= 0 && j < NS) g_S[j] = 0.f;
}

// C[M,N] = A[M,K] @ B[N,K]^T ; K % 16 == 0
__global__ __launch_bounds__(256) void sgemm_nt(
    int M, int N, int K,
    const float* __restrict__ A, const float* __restrict__ B,
    float* __restrict__ C, int ldc)
{
    __shared__ float As[16][132];
    __shared__ float Bs[16][68];
    const int tid = threadIdx.x;
    const int tx = tid & 15, ty = tid >> 4;
    const int m0 = blockIdx.y*128, n0 = blockIdx.x*64;
    float acc[8][4];
#pragma unroll
    for (int i=0;i<8;i++)
#pragma unroll
        for (int j=0;j<4;j++) acc[i][j]=0.f;

    for (int k0=0;k0<K;k0+=16) {
#pragma unroll
        for (int i=0;i<2;i++) {
            int idx = tid + i*256;
            int ar = idx >> 2, ac = (idx & 3) << 2;
            int gm = m0 + ar;
            float4 v = make_float4(0.f,0.f,0.f,0.f);
            if (gm < M) v = *(const float4*)(A + (size_t)gm*K + k0 + ac);
            As[ac+0][ar]=v.x; As[ac+1][ar]=v.y; As[ac+2][ar]=v.z; As[ac+3][ar]=v.w;
        }
        {
            int br = tid >> 2, bc = (tid & 3) << 2;
            int gn = n0 + br;
            float4 v = make_float4(0.f,0.f,0.f,0.f);
            if (gn < N) v = *(const float4*)(B + (size_t)gn*K + k0 + bc);
            Bs[bc+0][br]=v.x; Bs[bc+1][br]=v.y; Bs[bc+2][br]=v.z; Bs[bc+3][br]=v.w;
        }
        __syncthreads();
#pragma unroll
        for (int kk=0;kk<16;kk++) {
            float a[8], bb[4];
#pragma unroll
            for (int i=0;i<8;i++) a[i] = As[kk][ty*8+i];
            float4 bv = *(const float4*)&Bs[kk][tx*4];
            bb[0]=bv.x; bb[1]=bv.y; bb[2]=bv.z; bb[3]=bv.w;
#pragma unroll
            for (int i=0;i<8;i++)
#pragma unroll
                for (int j=0;j<4;j++) acc[i][j] = fmaf(a[i], bb[j], acc[i][j]);
        }
        __syncthreads();
    }
#pragma unroll
    for (int i=0;i<8;i++) {
        int gm = m0 + ty*8 + i;
        if (gm < M)
#pragma unroll
            for (int j=0;j<4;j++) {
                int gn = n0 + tx*4 + j;
                if (gn < N) C[(size_t)gm*ldc + gn] = acc[i][j];
            }
    }
}

// per-token: B,C,dt -> g_dA=exp(dt*A), g_dtB=dt*B, g_C=0.5*C (biscan scale folded)
__global__ __launch_bounds__(QPx) void precompute_kernel(
    const float* __restrict__ dist, const float* __restrict__ W_bc,
    const float* __restrict__ W_dt, const float* __restrict__ dt_bias,
    const float* __restrict__ A_log)
{
    const int bt = blockIdx.x;
    const int n  = threadIdx.x;
    __shared__ float swbc[32], swdt[128], sdtb[8], sA[8], stok[10];
    if (n < 32) swbc[n] = W_bc[n];
    if (n >= 32 && n < 160) swdt[n-32] = W_dt[n-32];
    if (n >= 160 && n < 168) {
        sdtb[n-160] = dt_bias[n-160];
        sA[n-160]   = -expf(A_log[n-160]);
    }
    if (n >= 168 && n < 178) stok[n-168] = g_zx[(size_t)bt*LDZ + 1024 + (n-168)];
    __syncthreads();

    const bool valid = (n < QQx);
    float d[16];
    if (valid) {
        const float* dp = dist + ((size_t)bt*QQx + n)*NDx;
        ld4(dp,d); ld4(dp+4,d+4); ld4(dp+8,d+8); ld4(dp+12,d+12);
    } else {
#pragma unroll
        for (int i=0;i<16;i++) d[i]=0.f;
    }
    float bc0=0.f, bc1=0.f;
#pragma unroll
    for (int i=0;i<16;i++) {
        bc0 = fmaf(d[i], swbc[i],    bc0);
        bc1 = fmaf(d[i], swbc[16+i], bc1);
    }
    float Bv = bc0 + stok[0];
    float Cv = bc1 + stok[1];
    g_C[(size_t)bt*QPx + n] = valid ? 0.5f*Cv : 0.f;
#pragma unroll
    for (int h=0;h<8;h++) {
        float db = 0.f;
#pragma unroll
        for (int i=0;i<16;i++) db = fmaf(d[i], swdt[h*16+i], db);
        float v  = db + stok[2+h] + sdtb[h];
        float dt = (v > 20.f) ? v : log1pf(expf(v));
        size_t o = ((size_t)bt*HHx + h)*QPx + n;
        g_dA[o]  = valid ? expf(dt*sA[h]) : 0.f;
        g_dtB[o] = valid ? dt*Bv : 0.f;
    }
}

// bidirectional scan v3: 128 blocks = (pg4, h8, b2, dir2); 640 thr (20 warps);
// thread tile 2p x 4n; 4-deep register pipeline (prefetch distance = 4 steps).
__global__ __launch_bounds__(640, 1) void scan_kernel() {
    const int bx  = blockIdx.x;
    const int pg  = bx & 3;
    const int h   = (bx >> 2) & 7;
    const int b   = (bx >> 5) & 1;
    const int dir = (bx >> 6) & 1;

    const int tid = threadIdx.x, w = tid >> 5, lane = tid & 31;
    const int wn = w >> 1, wp = w & 1;
    const int p_pair = lane >> 3, n_sub = lane & 7;
    const int n0 = wn*32 + n_sub*4;
    const int p0 = pg*16 + wp*8 + p_pair*2;

    float S0[4], S1[4];
#pragma unroll
    for (int j=0;j<4;j++) {
        int n = n0 + j;
        if (n < QQx) {
            const float* ip = &g_init[((size_t)(b*QQx+n))*DIx + h*PPx + p0];
            S0[j] = ip[0]; S1[j] = ip[1];
        } else { S0[j] = 0.f; S1[j] = 0.f; }
    }

    const int bL = b*LLx;
    const int t0 = dir ? (LLx-1) : 0;
    const int stp = dir ? -1 : 1;
    const long dA_s = (long)stp*(HHx*QPx);
    const long dC_s = (long)stp*QPx;
    const long dX_s = (long)stp*LDZ;
    const long dY_s = (long)stp*DIx;

    const float* pA = g_dA  + ((size_t)(bL+t0)*HHx + h)*QPx + n0;
    const float* pU = g_dtB + ((size_t)(bL+t0)*HHx + h)*QPx + n0;
    const float* pC = g_C   + (size_t)(bL+t0)*QPx + n0;
    const float* pX = g_zx  + (size_t)(bL+t0)*LDZ + DIx + h*PPx + p0;
    float*       pY = g_y   + (size_t)(bL+t0)*DIx + h*PPx + p0;

    float av[4][4], uv[4][4], cv[4][4], xv[4][2];
    // prologue: fill 4-deep pipeline (steps 0..3); pointers end at step 4
#pragma unroll
    for (int i=0;i<4;i++) {
        ld4(pA, av[i]); ld4(pU, uv[i]); ld4(pC, cv[i]);
        float2 t = *(const float2*)pX; xv[i][0]=t.x; xv[i][1]=t.y;
        pA += dA_s; pU += dA_s; pC += dC_s; pX += dX_s;
    }

    for (int s = 0; s < LLx; s += 4) {
        const bool pf = (s + 4 < LLx);
#pragma unroll
        for (int i=0;i<4;i++) {
            float yp0 = 0.f, yp1 = 0.f;
#pragma unroll
            for (int j=0;j<4;j++) {
                float s0 = fmaf(S0[j], av[i][j], uv[i][j]*xv[i][0]);
                float s1 = fmaf(S1[j], av[i][j], uv[i][j]*xv[i][1]);
                S0[j]=s0; S1[j]=s1;
                yp0 = fmaf(s0, cv[i][j], yp0);
                yp1 = fmaf(s1, cv[i][j], yp1);
            }
            // prefetch step s+4+i (issued early, before the shfl chain)
            if (pf) {
                ld4(pA, av[i]); ld4(pU, uv[i]); ld4(pC, cv[i]);
                float2 t = *(const float2*)pX; xv[i][0]=t.x; xv[i][1]=t.y;
                pA += dA_s; pU += dA_s; pC += dC_s; pX += dX_s;
            }
            yp0 += __shfl_xor_sync(0xffffffffu, yp0, 4);
            yp1 += __shfl_xor_sync(0xffffffffu, yp1, 4);
            yp0 += __shfl_xor_sync(0xffffffffu, yp0, 2);
            yp1 += __shfl_xor_sync(0xffffffffu, yp1, 2);
            yp0 += __shfl_xor_sync(0xffffffffu, yp0, 1);
            yp1 += __shfl_xor_sync(0xffffffffu, yp1, 1);
            if (n_sub == 0) {
                atomicAdd(pY,   yp0);
                atomicAdd(pY+1, yp1);
            }
            pY += dY_s;
        }
    }

#pragma unroll
    for (int j=0;j<4;j++) {
        int n = n0 + j;
        if (n < QQx) {
            float* sp = &g_S[((size_t)(b*QQx+n))*DIx + h*PPx + p0];
            atomicAdd(sp,   0.5f*S0[j]);
            atomicAdd(sp+1, 0.5f*S1[j]);
        }
    }
}

__global__ __launch_bounds__(256) void gate_rms_kernel(
    const float* __restrict__ Dv, const float* __restrict__ knw)
{
    const int row = blockIdx.x, tid = threadIdx.x;
    float g[2]; float ss = 0.f;
#pragma unroll
    for (int e2=0;e2<2;e2++) {
        int e = tid + e2*256;
        float y = g_y [(size_t)row*DIx + e];
        float x = g_zx[(size_t)row*LDZ + DIx + e];
        float z = g_zx[(size_t)row*LDZ + e];
        float gg = (y + x*Dv[e>>6]) * (z / (1.f + expf(-z)));
        g[e2] = gg;
        ss += gg*gg;
    }
#pragma unroll
    for (int o=16;o;o>>=1) ss += __shfl_xor_sync(0xffffffffu, ss, o);
    __shared__ float red[8];
    if ((tid & 31) == 0) red[tid>>5] = ss;
    __syncthreads();
    if (tid == 0) {
        float tot = 0.f;
#pragma unroll
        for (int i=0;i<8;i++) tot += red[i];
        red[0] = rsqrtf(tot/512.f + 1e-5f);
    }
    __syncthreads();
    float sc = red[0];
#pragma unroll
    for (int e2=0;e2<2;e2++) {
        int e = tid + e2*256;
        g_kf[(size_t)row*DIx + e] = g[e2]*sc*knw[e];
    }
}

__global__ __launch_bounds__(256) void lnorm_kernel(
    const float* __restrict__ wn, const float* __restrict__ bn)
{
    const int row = blockIdx.x, tid = threadIdx.x;
    float v[2]; float s1 = 0.f, s2 = 0.f;
#pragma unroll
    for (int e2=0;e2<2;e2++) {
        int e = tid + e2*256;
        float x = g_S[(size_t)row*DIx + e];
        v[e2] = x; s1 += x; s2 += x*x;
    }
#pragma unroll
    for (int o=16;o;o>>=1) {
        s1 += __shfl_xor_sync(0xffffffffu, s1, o);
        s2 += __shfl_xor_sync(0xffffffffu, s2, o);
    }
    __shared__ float r1[8], r2[8];
    if ((tid & 31) == 0) { r1[tid>>5] = s1; r2[tid>>5] = s2; }
    __syncthreads();
    __shared__ float smu, sisd;
    if (tid == 0) {
        float a=0.f, bq=0.f;
#pragma unroll
        for (int i=0;i<8;i++) { a += r1[i]; bq += r2[i]; }
        float mu = a/512.f;
        smu = mu;
        sisd = rsqrtf(bq/512.f - mu*mu + 1e-5f);
    }
    __syncthreads();
    float mu = smu, isd = sisd;
#pragma unroll
    for (int e2=0;e2<2;e2++) {
        int e = tid + e2*256;
        g_ln[(size_t)row*DIx + e] = (v[e2]-mu)*isd*wn[e] + bn[e];
    }
}

extern "C" void kernel_launch(void* const* d_in, const int* in_sizes, int n_in,
                              void* d_out, int out_size) {
    const float* in_key    = (const float*)d_in[0];
    const float* in_query  = (const float*)d_in[1];
    const float* dist      = (const float*)d_in[2];
    const float* W_key     = (const float*)d_in[3];
    const float* W_query   = (const float*)d_in[4];
    const float* W_bc      = (const float*)d_in[5];
    const float* W_dt      = (const float*)d_in[6];
    const float* dt_bias   = (const float*)d_in[7];
    const float* A_log     = (const float*)d_in[8];
    const float* Dv        = (const float*)d_in[9];
    const float* W_out_key = (const float*)d_in[10];
    const float* W_out_qry = (const float*)d_in[11];
    const float* key_nw    = (const float*)d_in[12];
    const float* q_nw      = (const float*)d_in[13];
    const float* q_nb      = (const float*)d_in[14];
    float* out = (float*)d_out;

    float *p_zx, *p_init, *p_kf, *p_ln;
    cudaGetSymbolAddress((void**)&p_zx,   g_zx);
    cudaGetSymbolAddress((void**)&p_init, g_init);
    cudaGetSymbolAddress((void**)&p_kf,   g_kf);
    cudaGetSymbolAddress((void**)&p_ln,   g_ln);

    zero_kernel<<<(NTOK*DIx + NQx*DIx + 255)/256, 256>>>();
    sgemm_nt<<<dim3(17,32), 256>>>(NTOK, 1034, 256, in_key,   W_key,   p_zx,   LDZ);
    sgemm_nt<<<dim3(8,5),   256>>>(NQx,  512,  256, in_query, W_query, p_init, DIx);
    precompute_kernel<<<NTOK, QPx>>>(dist, W_bc, W_dt, dt_bias, A_log);
    scan_kernel<<<128, 640>>>();
    gate_rms_kernel<<<NTOK, 256>>>(Dv, key_nw);
    lnorm_kernel<<<NQx, 256>>>(q_nw, q_nb);
    sgemm_nt<<<dim3(4,32), 256>>>(NTOK, 256, 512, p_kf, W_out_key, out, 256);
    sgemm_nt<<<dim3(4,5),  256>>>(NQx,  256, 512, p_ln, W_out_qry, out + (size_t)NTOK*256, 256);
}